// round 4
// baseline (speedup 1.0000x reference)
#include <cuda_runtime.h>

// ---------------- problem constants ----------------
static constexpr int NNODE = 10000;
static constexpr int NEDGE = 50000;
static constexpr int NSC   = 48;    // NS
static constexpr int NVC   = 10;    // NV
static constexpr int HID   = 128;
static constexpr int WTOT  = 3364;  // 2304 + 480 + 100 + 480
static constexpr int OFF2  = 2304;
static constexpr int OFF3  = 2784;
static constexpr int OFF4  = 2884;
static constexpr int TB    = 128;                      // edges per tile
static constexpr int NBLK  = (NEDGE + TB - 1) / TB;    // 391

#define EPS_BN     1e-5f
#define INV_SQRT3  0.57735026918962576f
#define NORM01     0.13130643285972254f   /* 1/sqrt(58) */

// ---------------- scratch (static device memory; no cudaMalloc) ----------------
__device__ float g_hT[(size_t)HID * NEDGE];   // h transposed [k][e], 25.6 MB
__device__ float g_sum[(size_t)NNODE * 78];   // per-node message sums
__device__ float g_cnt[NNODE];                // per-node edge counts
__device__ float g_stats[106];                // [0:48) sum_s, [48:96) sumsq_s, [96:106) sum v^2

// ---------------- K0: zero scratch ----------------
__global__ void k_zero() {
  int idx = blockIdx.x * blockDim.x + threadIdx.x;
  int stride = gridDim.x * blockDim.x;
  for (int i = idx; i < NNODE * 78; i += stride) g_sum[i] = 0.f;
  for (int i = idx; i < NNODE; i += stride) g_cnt[i] = 0.f;
  if (idx < 106) g_stats[idx] = 0.f;
}

// ---------------- K1: h = relu(edge_attr @ W1 + b1), stored transposed ----------------
static constexpr int K1_SMEM = (128 * 132 + 128 * 128) * 4;

__global__ __launch_bounds__(256) void k_gemm1(const float* __restrict__ A,
                                               const float* __restrict__ W1,
                                               const float* __restrict__ b1) {
  extern __shared__ float sm[];
  float* sAT = sm;              // [128 k][132 e-padded]
  float* sB  = sm + 128 * 132;  // [128 k][128 c]
  int tid = threadIdx.x;
  int e0 = blockIdx.x * TB;

  for (int idx = tid; idx < 128 * 128; idx += 256) {
    int e = idx >> 7, k = idx & 127;
    sAT[k * 132 + e] = (e0 + e < NEDGE) ? A[(size_t)(e0 + e) * 128 + k] : 0.f;
    sB[idx] = W1[idx];
  }
  __syncthreads();

  int ty = tid >> 4, tx = tid & 15;
  int ea = ty * 4, ca = tx * 4;
  float C[8][8];
#pragma unroll
  for (int i = 0; i < 8; ++i)
#pragma unroll
    for (int j = 0; j < 8; ++j) C[i][j] = 0.f;

#pragma unroll 4
  for (int k = 0; k < 128; ++k) {
    float4 A0 = *(const float4*)&sAT[k * 132 + ea];
    float4 A1 = *(const float4*)&sAT[k * 132 + 64 + ea];
    float4 B0 = *(const float4*)&sB[k * 128 + ca];
    float4 B1 = *(const float4*)&sB[k * 128 + 64 + ca];
    float a[8] = {A0.x, A0.y, A0.z, A0.w, A1.x, A1.y, A1.z, A1.w};
    float b[8] = {B0.x, B0.y, B0.z, B0.w, B1.x, B1.y, B1.z, B1.w};
#pragma unroll
    for (int i = 0; i < 8; ++i)
#pragma unroll
      for (int j = 0; j < 8; ++j) C[i][j] = fmaf(a[i], b[j], C[i][j]);
  }
  __syncthreads();  // done reading sAT; reuse as transpose staging [c][e]

#pragma unroll
  for (int j = 0; j < 8; ++j) {
    int c = (j < 4) ? ca + j : 60 + ca + j;
    float bj = b1[c];
#pragma unroll
    for (int i = 0; i < 8; ++i) {
      int e = (i < 4) ? ea + i : 60 + ea + i;
      float v = C[i][j] + bj;
      sAT[c * 132 + e] = v > 0.f ? v : 0.f;
    }
  }
  __syncthreads();
  for (int idx = tid; idx < 128 * 128; idx += 256) {
    int c = idx >> 7, e = idx & 127;
    if (e0 + e < NEDGE) g_hT[(size_t)c * NEDGE + e0 + e] = sAT[c * 132 + e];
  }
}

// ---------------- K2: fused GEMM2 + tensor product + scatter ----------------
static constexpr int S_HT  = 0;               // 129*132
static constexpr int S_W   = 129 * 132;       // 129*128 (W2 chunk, reused as C-stage)
static constexpr int S_S   = S_W + 129 * 128; // 128*48 s_in
static constexpr int S_DOT = S_S + 128 * 48;  // 128*10
static constexpr int S_VIN = S_DOT + 128 * 10;// 128*30
static constexpr int S_SH  = S_VIN + 128 * 30;// 128*4
static constexpr int S_AC0 = S_SH + 128 * 4;  // 128*48
static constexpr int S_YA  = S_AC0 + 128 * 48;// 128*10
static constexpr int S_YB  = S_YA + 128 * 10; // 128*30
static constexpr int S_TOT = S_YB + 128 * 30; // 56580 floats
static constexpr int K2_SMEM = S_TOT * 4;     // 226320 B  (< 227 KB limit)

__global__ __launch_bounds__(256) void k_fused(const int* __restrict__ eidx,
                                               const float* __restrict__ node_attr,
                                               const float* __restrict__ edge_sh,
                                               const float* __restrict__ W2,
                                               const float* __restrict__ b2) {
  extern __shared__ float sm[];
  float* sHT  = sm + S_HT;
  float* sW   = sm + S_W;
  float* sS   = sm + S_S;
  float* sDot = sm + S_DOT;
  float* sVin = sm + S_VIN;
  float* sSh  = sm + S_SH;
  float* sAc0 = sm + S_AC0;
  float* sYa  = sm + S_YA;
  float* sYb  = sm + S_YB;

  int tid = threadIdx.x;
  int e0 = blockIdx.x * TB;

  // load h^T tile (row 128 = 1.0 for bias folding)
  for (int idx = tid; idx < 128 * 128; idx += 256) {
    int k = idx >> 7, e = idx & 127;
    sHT[k * 132 + e] = (e0 + e < NEDGE) ? g_hT[(size_t)k * NEDGE + e0 + e] : 0.f;
  }
  if (tid < 128) sHT[128 * 132 + tid] = 1.0f;

  // zero accumulators (sAc0, sYa, sYb are contiguous)
  for (int idx = tid; idx < 128 * (48 + 10 + 30); idx += 256) sAc0[idx] = 0.f;

  // left vectors
  {
    int e = tid >> 1, half = tid & 1;
    int eg = e0 + e;
    if (eg < NEDGE) {
      int dst = eidx[NEDGE + eg];
      const float* x = node_attr + (size_t)dst * 78;
      for (int u = half * 24; u < half * 24 + 24; ++u) sS[e * 48 + u] = x[u];
      for (int m = half * 15; m < half * 15 + 15; ++m) sVin[e * 30 + m] = x[48 + m];
      if (!half)
        for (int i = 0; i < 4; ++i) sSh[e * 4 + i] = edge_sh[(size_t)eg * 4 + i];
    }
  }
  __syncthreads();
  {
    int e = tid >> 1, half = tid & 1;
    float s1 = sSh[e * 4 + 1], s2 = sSh[e * 4 + 2], s3 = sSh[e * 4 + 3];
    for (int u = half * 5; u < half * 5 + 5; ++u)
      sDot[e * 10 + u] = (sVin[e * 30 + u * 3] * s1 + sVin[e * 30 + u * 3 + 1] * s2 +
                          sVin[e * 30 + u * 3 + 2] * s3) * INV_SQRT3;
  }

  int ty = tid >> 4, tx = tid & 15;
  int ea = ty * 4, ca = tx * 4;
  int e_ = tid >> 1, half_ = tid & 1;

  // chunk schedule: 4x w2(120) -> [scale sS by sh0] -> 18x w1(128) -> 4x w4(120) -> 1x w3(100)
  for (int ci = 0; ci < 27; ++ci) {
    int type, jstart, cnt, rel;
    if (ci < 4)       { type = 2; rel = ci * 120;        jstart = OFF2 + rel; cnt = 120; }
    else if (ci < 22) { type = 1; rel = (ci - 4) * 128;  jstart = rel;        cnt = 128; }
    else if (ci < 26) { type = 4; rel = (ci - 22) * 120; jstart = OFF4 + rel; cnt = 120; }
    else              { type = 3; rel = 0;               jstart = OFF3;       cnt = 100; }

    __syncthreads();  // prev epilogue done with sW
    for (int idx = tid; idx < 129 * 128; idx += 256) {
      int k = idx >> 7, j = idx & 127;
      float v = 0.f;
      if (j < cnt) v = (k < 128) ? W2[(size_t)k * WTOT + jstart + j] : b2[jstart + j];
      sW[idx] = v;
    }
    __syncthreads();

    float C[8][8];
#pragma unroll
    for (int i = 0; i < 8; ++i)
#pragma unroll
      for (int j = 0; j < 8; ++j) C[i][j] = 0.f;

#pragma unroll 3
    for (int k = 0; k < 129; ++k) {
      float4 A0 = *(const float4*)&sHT[k * 132 + ea];
      float4 A1 = *(const float4*)&sHT[k * 132 + 64 + ea];
      float4 B0 = *(const float4*)&sW[k * 128 + ca];
      float4 B1 = *(const float4*)&sW[k * 128 + 64 + ca];
      float a[8] = {A0.x, A0.y, A0.z, A0.w, A1.x, A1.y, A1.z, A1.w};
      float b[8] = {B0.x, B0.y, B0.z, B0.w, B1.x, B1.y, B1.z, B1.w};
#pragma unroll
      for (int i = 0; i < 8; ++i)
#pragma unroll
        for (int j = 0; j < 8; ++j) C[i][j] = fmaf(a[i], b[j], C[i][j]);
    }
    __syncthreads();  // done reading sW as weights; reuse as C-stage [e][jj]

#pragma unroll
    for (int i = 0; i < 8; ++i) {
      int e = (i < 4) ? ea + i : 60 + ea + i;
      *(float4*)&sW[e * 128 + ca]      = make_float4(C[i][0], C[i][1], C[i][2], C[i][3]);
      *(float4*)&sW[e * 128 + 64 + ca] = make_float4(C[i][4], C[i][5], C[i][6], C[i][7]);
    }
    __syncthreads();

    // ownership-partitioned epilogue (2 threads per edge, no atomics)
    if (type == 1 || type == 4) {
      const float* mult = (type == 1) ? (sS + e_ * 48) : (sDot + e_ * 10);
      int umax = (type == 1) ? 47 : 9;
      const float* Cs = sW + e_ * 128 - rel;  // index with u*48+v (>= rel)
#pragma unroll 4
      for (int vv = 0; vv < 24; ++vv) {
        int v = half_ * 24 + vv;
        int d = rel - v;
        int u0 = d > 0 ? (d + 47) / 48 : 0;
        int u1 = (rel + cnt - 1 - v) / 48; if (u1 > umax) u1 = umax;
        float p = 0.f;
        for (int u = u0; u <= u1; ++u) p = fmaf(Cs[u * 48 + v], mult[u], p);
        sAc0[e_ * 48 + v] += p;
      }
    } else if (type == 2) {
      const float* Cs = sW + e_ * 128 - rel;
#pragma unroll
      for (int vv = 0; vv < 5; ++vv) {
        int v = half_ * 5 + vv;
        int d = rel - v;
        int u0 = d > 0 ? (d + 9) / 10 : 0;
        int u1 = (rel + cnt - 1 - v) / 10; if (u1 > 47) u1 = 47;
        float p = 0.f;
        for (int u = u0; u <= u1; ++u) p = fmaf(Cs[u * 10 + v], sS[e_ * 48 + u], p);
        sYa[e_ * 10 + v] += p;
      }
    } else {  // w3
      const float* Cs = sW + e_ * 128;
#pragma unroll
      for (int vv = 0; vv < 5; ++vv) {
        int v = half_ * 5 + vv;
        float y0 = 0.f, y1 = 0.f, y2 = 0.f;
#pragma unroll
        for (int u = 0; u < 10; ++u) {
          float wv = Cs[u * 10 + v];
          y0 = fmaf(wv, sVin[e_ * 30 + u * 3 + 0], y0);
          y1 = fmaf(wv, sVin[e_ * 30 + u * 3 + 1], y1);
          y2 = fmaf(wv, sVin[e_ * 30 + u * 3 + 2], y2);
        }
        sYb[e_ * 30 + v * 3 + 0] += y0;
        sYb[e_ * 30 + v * 3 + 1] += y1;
        sYb[e_ * 30 + v * 3 + 2] += y2;
      }
    }

    if (ci == 3) {  // w2 phase done -> scale s by sh0 for the w1 phase
      __syncthreads();
      float s0 = sSh[e_ * 4 + 0];
      for (int vv = 0; vv < 24; ++vv) sS[e_ * 48 + half_ * 24 + vv] *= s0;
    }
  }
  __syncthreads();

  // final per-edge output + scatter to node sums
  {
    int eg = e0 + e_;
    if (eg < NEDGE) {
      int src = eidx[eg];
      float s0 = sSh[e_ * 4], s1 = sSh[e_ * 4 + 1], s2 = sSh[e_ * 4 + 2], s3 = sSh[e_ * 4 + 3];
      float* dp = g_sum + (size_t)src * 78;
      for (int vv = 0; vv < 24; ++vv) {
        int v = half_ * 24 + vv;
        atomicAdd(&dp[v], sAc0[e_ * 48 + v] * NORM01);
      }
      for (int vv = 0; vv < 5; ++vv) {
        int v = half_ * 5 + vv;
        float ya = sYa[e_ * 10 + v];
        atomicAdd(&dp[48 + v * 3 + 0], (ya * s1 + sYb[e_ * 30 + v * 3 + 0] * s0) * NORM01);
        atomicAdd(&dp[48 + v * 3 + 1], (ya * s2 + sYb[e_ * 30 + v * 3 + 1] * s0) * NORM01);
        atomicAdd(&dp[48 + v * 3 + 2], (ya * s3 + sYb[e_ * 30 + v * 3 + 2] * s0) * NORM01);
      }
      if (!half_) atomicAdd(&g_cnt[src], 1.f);
    }
  }
}

// ---------------- K3: node finalize (mean + residual) + BN statistics ----------------
__global__ __launch_bounds__(256) void k_node(const float* __restrict__ node_attr,
                                              float* __restrict__ dout) {
  __shared__ float sP[106];
  int tid = threadIdx.x;
  if (tid < 106) sP[tid] = 0.f;
  __syncthreads();

  int n = blockIdx.x * blockDim.x + tid;
  bool valid = n < NNODE;
  float inv = 1.f;
  if (valid) inv = 1.f / fmaxf(g_cnt[n], 1.f);
  const float* srow  = g_sum + (valid ? (size_t)n * 78 : 0);
  const float* narow = node_attr + (valid ? (size_t)n * 78 : 0);

  for (int v = 0; v < 48; ++v) {
    float val = 0.f;
    if (valid) { val = srow[v] * inv + narow[v]; dout[(size_t)n * 78 + v] = val; }
    float s = val, q = val * val;
#pragma unroll
    for (int o = 16; o; o >>= 1) {
      s += __shfl_xor_sync(0xffffffffu, s, o);
      q += __shfl_xor_sync(0xffffffffu, q, o);
    }
    if ((tid & 31) == 0) { atomicAdd(&sP[v], s); atomicAdd(&sP[48 + v], q); }
  }
  for (int u = 0; u < 10; ++u) {
    float q = 0.f;
    for (int i = 0; i < 3; ++i) {
      float val = 0.f;
      int c = 48 + u * 3 + i;
      if (valid) { val = srow[c] * inv + narow[c]; dout[(size_t)n * 78 + c] = val; }
      q += val * val;
    }
#pragma unroll
    for (int o = 16; o; o >>= 1) q += __shfl_xor_sync(0xffffffffu, q, o);
    if ((tid & 31) == 0) atomicAdd(&sP[96 + u], q);
  }
  __syncthreads();
  if (tid < 106) atomicAdd(&g_stats[tid], sP[tid]);
}

// ---------------- K4: apply batch norm in place ----------------
__global__ void k_bn(const float* __restrict__ bnw, const float* __restrict__ bnb,
                     float* __restrict__ dout) {
  int idx = blockIdx.x * blockDim.x + threadIdx.x;
  if (idx >= NNODE * 78) return;
  int c = idx % 78;
  float x = dout[idx];
  if (c < 48) {
    float mean = g_stats[c] * (1.f / NNODE);
    float var  = g_stats[48 + c] * (1.f / NNODE) - mean * mean;
    dout[idx] = (x - mean) * rsqrtf(var + EPS_BN) * bnw[c] + bnb[c];
  } else {
    int u = (c - 48) / 3;
    float vn = g_stats[96 + u] * (1.f / (3.f * NNODE));
    dout[idx] = x * rsqrtf(vn + EPS_BN) * bnw[48 + u];
  }
}

// ---------------- launch ----------------
extern "C" void kernel_launch(void* const* d_in, const int* in_sizes, int n_in,
                              void* d_out, int out_size) {
  const float* node_attr  = (const float*)d_in[0];
  const int*   edge_index = (const int*)d_in[1];
  const float* edge_attr  = (const float*)d_in[2];
  const float* edge_sh    = (const float*)d_in[3];
  const float* fc_w1      = (const float*)d_in[4];
  const float* fc_b1      = (const float*)d_in[5];
  const float* fc_w2      = (const float*)d_in[6];
  const float* fc_b2      = (const float*)d_in[7];
  const float* bn_w       = (const float*)d_in[8];
  const float* bn_b       = (const float*)d_in[9];
  float* out = (float*)d_out;

  cudaFuncSetAttribute(k_gemm1, cudaFuncAttributeMaxDynamicSharedMemorySize, K1_SMEM);
  cudaFuncSetAttribute(k_fused, cudaFuncAttributeMaxDynamicSharedMemorySize, K2_SMEM);

  k_zero<<<256, 256>>>();
  k_gemm1<<<NBLK, 256, K1_SMEM>>>(edge_attr, fc_w1, fc_b1);
  k_fused<<<NBLK, 256, K2_SMEM>>>(edge_index, node_attr, edge_sh, fc_w2, fc_b2);
  k_node<<<(NNODE + 255) / 256, 256>>>(node_attr, out);
  k_bn<<<(NNODE * 78 + 255) / 256, 256>>>(bn_w, bn_b, out);
}

// round 5
// speedup vs baseline: 1.4280x; 1.4280x over previous
#include <cuda_runtime.h>

// ---------------- problem constants ----------------
static constexpr int NNODE = 10000;
static constexpr int NEDGE = 50000;
static constexpr int HID   = 128;
static constexpr int WTOT  = 3364;  // 2304 + 480 + 100 + 480
static constexpr int OFF2  = 2304;
static constexpr int OFF3  = 2784;
static constexpr int OFF4  = 2884;
static constexpr int TB    = 128;                      // edges per tile
static constexpr int NBLK  = (NEDGE + TB - 1) / TB;    // 391

#define EPS_BN     1e-5f
#define INV_SQRT3  0.57735026918962576f
#define NORM01     0.13130643285972254f   /* 1/sqrt(58) */

// ---------------- packed f32x2 helpers (sm_103a FFMA2 path) ----------------
__device__ __forceinline__ unsigned long long f2_fma(unsigned long long a,
                                                     unsigned long long b,
                                                     unsigned long long c) {
  unsigned long long d;
  asm("fma.rn.f32x2 %0, %1, %2, %3;" : "=l"(d) : "l"(a), "l"(b), "l"(c));
  return d;
}
__device__ __forceinline__ unsigned long long f2_dup(float x) {
  unsigned long long d;
  asm("mov.b64 %0, {%1, %1};" : "=l"(d) : "f"(x));
  return d;
}
__device__ __forceinline__ float2 f2_unpack(unsigned long long v) {
  float2 f;
  asm("mov.b64 {%0, %1}, %2;" : "=f"(f.x), "=f"(f.y) : "l"(v));
  return f;
}

// ---------------- scratch (static device memory; no cudaMalloc) ----------------
__device__ float g_hT[(size_t)HID * NEDGE];   // h transposed [k][e]
__device__ float g_sum[(size_t)NNODE * 78];   // per-node message sums
__device__ float g_cnt[NNODE];                // per-node edge counts
__device__ float g_stats[106];                // [0:48) sum_s, [48:96) sumsq_s, [96:106) sum v^2

// ---------------- K0: zero scratch ----------------
__global__ void k_zero() {
  int idx = blockIdx.x * blockDim.x + threadIdx.x;
  int stride = gridDim.x * blockDim.x;
  for (int i = idx; i < NNODE * 78; i += stride) g_sum[i] = 0.f;
  for (int i = idx; i < NNODE; i += stride) g_cnt[i] = 0.f;
  if (idx < 106) g_stats[idx] = 0.f;
}

// ---------------- K1: h = relu(edge_attr @ W1 + b1), stored transposed ----------------
static constexpr int K1_SMEM = (128 * 132 + 128 * 128) * 4;

__global__ __launch_bounds__(512) void k_gemm1(const float* __restrict__ A,
                                               const float* __restrict__ W1,
                                               const float* __restrict__ b1) {
  extern __shared__ float sm[];
  float* sAT = sm;              // [128 k][132 e-padded]; reused as [e][132 c] staging
  float* sB  = sm + 128 * 132;  // [128 k][128 c]
  int tid = threadIdx.x;
  int e0 = blockIdx.x * TB;

  for (int idx = tid; idx < 128 * 128; idx += 512) {
    int e = idx >> 7, k = idx & 127;
    sAT[k * 132 + e] = (e0 + e < NEDGE) ? A[(size_t)(e0 + e) * 128 + k] : 0.f;
    sB[idx] = W1[idx];
  }
  __syncthreads();

  int w = tid >> 5, lane = tid & 31;
  int ea = w * 4;        // rows ea..ea+3 and 64+ea..64+ea+3
  int ca = lane * 4;     // cols ca..ca+3

  unsigned long long C2[4][4];
#pragma unroll
  for (int i = 0; i < 4; ++i)
#pragma unroll
    for (int j = 0; j < 4; ++j) C2[i][j] = 0ull;

#pragma unroll 3
  for (int k = 0; k < 128; ++k) {
    ulonglong2 a0 = *(const ulonglong2*)&sAT[k * 132 + ea];
    ulonglong2 a1 = *(const ulonglong2*)&sAT[k * 132 + 64 + ea];
    float4 B = *(const float4*)&sB[k * 128 + ca];
    unsigned long long bd0 = f2_dup(B.x), bd1 = f2_dup(B.y),
                       bd2 = f2_dup(B.z), bd3 = f2_dup(B.w);
    C2[0][0] = f2_fma(a0.x, bd0, C2[0][0]);
    C2[0][1] = f2_fma(a0.x, bd1, C2[0][1]);
    C2[0][2] = f2_fma(a0.x, bd2, C2[0][2]);
    C2[0][3] = f2_fma(a0.x, bd3, C2[0][3]);
    C2[1][0] = f2_fma(a0.y, bd0, C2[1][0]);
    C2[1][1] = f2_fma(a0.y, bd1, C2[1][1]);
    C2[1][2] = f2_fma(a0.y, bd2, C2[1][2]);
    C2[1][3] = f2_fma(a0.y, bd3, C2[1][3]);
    C2[2][0] = f2_fma(a1.x, bd0, C2[2][0]);
    C2[2][1] = f2_fma(a1.x, bd1, C2[2][1]);
    C2[2][2] = f2_fma(a1.x, bd2, C2[2][2]);
    C2[2][3] = f2_fma(a1.x, bd3, C2[2][3]);
    C2[3][0] = f2_fma(a1.y, bd0, C2[3][0]);
    C2[3][1] = f2_fma(a1.y, bd1, C2[3][1]);
    C2[3][2] = f2_fma(a1.y, bd2, C2[3][2]);
    C2[3][3] = f2_fma(a1.y, bd3, C2[3][3]);
  }
  __syncthreads();  // done reading sAT; reuse as [e][132 c] staging

  float b0 = b1[ca], bb1 = b1[ca + 1], bb2 = b1[ca + 2], bb3 = b1[ca + 3];
#pragma unroll
  for (int i = 0; i < 4; ++i) {
    int er = (i < 2) ? (ea + 2 * i) : (64 + ea + 2 * (i - 2));
    float2 f0 = f2_unpack(C2[i][0]);
    float2 f1 = f2_unpack(C2[i][1]);
    float2 f2v = f2_unpack(C2[i][2]);
    float2 f3 = f2_unpack(C2[i][3]);
    float4 r0 = make_float4(fmaxf(f0.x + b0, 0.f), fmaxf(f1.x + bb1, 0.f),
                            fmaxf(f2v.x + bb2, 0.f), fmaxf(f3.x + bb3, 0.f));
    float4 r1 = make_float4(fmaxf(f0.y + b0, 0.f), fmaxf(f1.y + bb1, 0.f),
                            fmaxf(f2v.y + bb2, 0.f), fmaxf(f3.y + bb3, 0.f));
    *(float4*)&sAT[er * 132 + ca]       = r0;
    *(float4*)&sAT[(er + 1) * 132 + ca] = r1;
  }
  __syncthreads();
  for (int idx = tid; idx < 128 * 128; idx += 512) {
    int c = idx & 127, e = idx >> 7;  // consecutive tid -> consecutive c? no:
  }
  // coalesced global store: consecutive threads -> consecutive e for fixed c
  for (int idx = tid; idx < 128 * 128; idx += 512) {
    int c = idx >> 7, e = idx & 127;
    if (e0 + e < NEDGE) g_hT[(size_t)c * NEDGE + e0 + e] = sAT[e * 132 + c];
  }
}

// ---------------- K2: fused GEMM2 + tensor product + scatter ----------------
static constexpr int S_HT  = 0;               // 129*132
static constexpr int S_W   = 129 * 132;       // 129*128 (W2 chunk, reused as C-stage)
static constexpr int S_S   = S_W + 129 * 128; // 128*48 s_in
static constexpr int S_DOT = S_S + 128 * 48;  // 128*10
static constexpr int S_VIN = S_DOT + 128 * 10;// 128*30
static constexpr int S_SH  = S_VIN + 128 * 30;// 128*4
static constexpr int S_AC0 = S_SH + 128 * 4;  // 128*48
static constexpr int S_YA  = S_AC0 + 128 * 48;// 128*10
static constexpr int S_YB  = S_YA + 128 * 10; // 128*30
static constexpr int S_TOT = S_YB + 128 * 30; // 56580 floats
static constexpr int K2_SMEM = S_TOT * 4;     // 226320 B

__global__ __launch_bounds__(512) void k_fused(const int* __restrict__ eidx,
                                               const float* __restrict__ node_attr,
                                               const float* __restrict__ edge_sh,
                                               const float* __restrict__ W2,
                                               const float* __restrict__ b2) {
  extern __shared__ float sm[];
  float* sHT  = sm + S_HT;
  float* sW   = sm + S_W;
  float* sS   = sm + S_S;
  float* sDot = sm + S_DOT;
  float* sVin = sm + S_VIN;
  float* sSh  = sm + S_SH;
  float* sAc0 = sm + S_AC0;
  float* sYa  = sm + S_YA;
  float* sYb  = sm + S_YB;

  int tid = threadIdx.x;
  int e0 = blockIdx.x * TB;

  // load h^T tile (row 128 = 1.0 for bias folding)
  for (int idx = tid; idx < 128 * 128; idx += 512) {
    int k = idx >> 7, e = idx & 127;
    sHT[k * 132 + e] = (e0 + e < NEDGE) ? g_hT[(size_t)k * NEDGE + e0 + e] : 0.f;
  }
  if (tid < 128) sHT[128 * 132 + tid] = 1.0f;

  // zero accumulators (sAc0, sYa, sYb are contiguous)
  for (int idx = tid; idx < 128 * (48 + 10 + 30); idx += 512) sAc0[idx] = 0.f;

  int e_ = tid >> 2, q = tid & 3;   // 4 owner threads per edge

  // left vectors
  {
    int eg = e0 + e_;
    if (eg < NEDGE) {
      int dst = eidx[NEDGE + eg];
      const float* x = node_attr + (size_t)dst * 78;
      for (int u = q * 12; u < q * 12 + 12; ++u) sS[e_ * 48 + u] = x[u];
      for (int m = q; m < 30; m += 4) sVin[e_ * 30 + m] = x[48 + m];
      if (q == 0)
        for (int i = 0; i < 4; ++i) sSh[e_ * 4 + i] = edge_sh[(size_t)eg * 4 + i];
    }
  }
  __syncthreads();
  {
    float s1 = sSh[e_ * 4 + 1], s2 = sSh[e_ * 4 + 2], s3 = sSh[e_ * 4 + 3];
    for (int u = q; u < 10; u += 4)
      sDot[e_ * 10 + u] = (sVin[e_ * 30 + u * 3] * s1 + sVin[e_ * 30 + u * 3 + 1] * s2 +
                           sVin[e_ * 30 + u * 3 + 2] * s3) * INV_SQRT3;
  }

  int w = tid >> 5, lane = tid & 31;
  int ea = w * 4;        // rows ea..ea+3 and 64+ea..64+ea+3
  int ca = lane * 4;     // cols ca..ca+3

  // chunk schedule: 4x w2(120) -> [scale sS by sh0] -> 18x w1(128) -> 4x w4(120) -> 1x w3(100)
  for (int ci = 0; ci < 27; ++ci) {
    int type, jstart, cnt, rel;
    if (ci < 4)       { type = 2; rel = ci * 120;        jstart = OFF2 + rel; cnt = 120; }
    else if (ci < 22) { type = 1; rel = (ci - 4) * 128;  jstart = rel;        cnt = 128; }
    else if (ci < 26) { type = 4; rel = (ci - 22) * 120; jstart = OFF4 + rel; cnt = 120; }
    else              { type = 3; rel = 0;               jstart = OFF3;       cnt = 100; }

    __syncthreads();  // prev epilogue done with sW
    for (int idx = tid; idx < 129 * 128; idx += 512) {
      int k = idx >> 7, j = idx & 127;
      float v = 0.f;
      if (j < cnt) v = (k < 128) ? W2[(size_t)k * WTOT + jstart + j] : b2[jstart + j];
      sW[idx] = v;
    }
    __syncthreads();

    unsigned long long C2[4][4];
#pragma unroll
    for (int i = 0; i < 4; ++i)
#pragma unroll
      for (int j = 0; j < 4; ++j) C2[i][j] = 0ull;

#pragma unroll 3
    for (int k = 0; k < 129; ++k) {
      ulonglong2 a0 = *(const ulonglong2*)&sHT[k * 132 + ea];
      ulonglong2 a1 = *(const ulonglong2*)&sHT[k * 132 + 64 + ea];
      float4 B = *(const float4*)&sW[k * 128 + ca];
      unsigned long long bd0 = f2_dup(B.x), bd1 = f2_dup(B.y),
                         bd2 = f2_dup(B.z), bd3 = f2_dup(B.w);
      C2[0][0] = f2_fma(a0.x, bd0, C2[0][0]);
      C2[0][1] = f2_fma(a0.x, bd1, C2[0][1]);
      C2[0][2] = f2_fma(a0.x, bd2, C2[0][2]);
      C2[0][3] = f2_fma(a0.x, bd3, C2[0][3]);
      C2[1][0] = f2_fma(a0.y, bd0, C2[1][0]);
      C2[1][1] = f2_fma(a0.y, bd1, C2[1][1]);
      C2[1][2] = f2_fma(a0.y, bd2, C2[1][2]);
      C2[1][3] = f2_fma(a0.y, bd3, C2[1][3]);
      C2[2][0] = f2_fma(a1.x, bd0, C2[2][0]);
      C2[2][1] = f2_fma(a1.x, bd1, C2[2][1]);
      C2[2][2] = f2_fma(a1.x, bd2, C2[2][2]);
      C2[2][3] = f2_fma(a1.x, bd3, C2[2][3]);
      C2[3][0] = f2_fma(a1.y, bd0, C2[3][0]);
      C2[3][1] = f2_fma(a1.y, bd1, C2[3][1]);
      C2[3][2] = f2_fma(a1.y, bd2, C2[3][2]);
      C2[3][3] = f2_fma(a1.y, bd3, C2[3][3]);
    }
    __syncthreads();  // done reading sW as weights; reuse as C-stage [e][jj]

#pragma unroll
    for (int i = 0; i < 4; ++i) {
      int er = (i < 2) ? (ea + 2 * i) : (64 + ea + 2 * (i - 2));
      float2 f0 = f2_unpack(C2[i][0]);
      float2 f1 = f2_unpack(C2[i][1]);
      float2 f2v = f2_unpack(C2[i][2]);
      float2 f3 = f2_unpack(C2[i][3]);
      *(float4*)&sW[er * 128 + ca]       = make_float4(f0.x, f1.x, f2v.x, f3.x);
      *(float4*)&sW[(er + 1) * 128 + ca] = make_float4(f0.y, f1.y, f2v.y, f3.y);
    }
    __syncthreads();

    // ownership-partitioned epilogue (4 threads per edge, no atomics)
    if (type == 1 || type == 4) {
      const float* mult = (type == 1) ? (sS + e_ * 48) : (sDot + e_ * 10);
      int umax = (type == 1) ? 47 : 9;
      const float* Cs = sW + e_ * 128 - rel;  // index with u*48+v (>= rel)
#pragma unroll 4
      for (int vv = 0; vv < 12; ++vv) {
        int v = q * 12 + vv;
        int d = rel - v;
        int u0 = d > 0 ? (d + 47) / 48 : 0;
        int u1 = (rel + cnt - 1 - v) / 48; if (u1 > umax) u1 = umax;
        float p = 0.f;
        for (int u = u0; u <= u1; ++u) p = fmaf(Cs[u * 48 + v], mult[u], p);
        sAc0[e_ * 48 + v] += p;
      }
    } else if (type == 2) {
      const float* Cs = sW + e_ * 128 - rel;
      for (int v = q; v < 10; v += 4) {
        int d = rel - v;
        int u0 = d > 0 ? (d + 9) / 10 : 0;
        int u1 = (rel + cnt - 1 - v) / 10; if (u1 > 47) u1 = 47;
        float p = 0.f;
        for (int u = u0; u <= u1; ++u) p = fmaf(Cs[u * 10 + v], sS[e_ * 48 + u], p);
        sYa[e_ * 10 + v] += p;
      }
    } else {  // w3
      const float* Cs = sW + e_ * 128;
      for (int v = q; v < 10; v += 4) {
        float y0 = 0.f, y1 = 0.f, y2 = 0.f;
#pragma unroll
        for (int u = 0; u < 10; ++u) {
          float wv = Cs[u * 10 + v];
          y0 = fmaf(wv, sVin[e_ * 30 + u * 3 + 0], y0);
          y1 = fmaf(wv, sVin[e_ * 30 + u * 3 + 1], y1);
          y2 = fmaf(wv, sVin[e_ * 30 + u * 3 + 2], y2);
        }
        sYb[e_ * 30 + v * 3 + 0] += y0;
        sYb[e_ * 30 + v * 3 + 1] += y1;
        sYb[e_ * 30 + v * 3 + 2] += y2;
      }
    }

    if (ci == 3) {  // w2 phase done -> scale s by sh0 for the w1 phase
      __syncthreads();
      float s0 = sSh[e_ * 4 + 0];
      for (int vv = 0; vv < 12; ++vv) sS[e_ * 48 + q * 12 + vv] *= s0;
    }
  }
  __syncthreads();

  // final per-edge output + scatter to node sums
  {
    int eg = e0 + e_;
    if (eg < NEDGE) {
      int src = eidx[eg];
      float s0 = sSh[e_ * 4], s1 = sSh[e_ * 4 + 1], s2 = sSh[e_ * 4 + 2], s3 = sSh[e_ * 4 + 3];
      float* dp = g_sum + (size_t)src * 78;
      for (int vv = 0; vv < 12; ++vv) {
        int v = q * 12 + vv;
        atomicAdd(&dp[v], sAc0[e_ * 48 + v] * NORM01);
      }
      for (int v = q; v < 10; v += 4) {
        float ya = sYa[e_ * 10 + v];
        atomicAdd(&dp[48 + v * 3 + 0], (ya * s1 + sYb[e_ * 30 + v * 3 + 0] * s0) * NORM01);
        atomicAdd(&dp[48 + v * 3 + 1], (ya * s2 + sYb[e_ * 30 + v * 3 + 1] * s0) * NORM01);
        atomicAdd(&dp[48 + v * 3 + 2], (ya * s3 + sYb[e_ * 30 + v * 3 + 2] * s0) * NORM01);
      }
      if (q == 0) atomicAdd(&g_cnt[src], 1.f);
    }
  }
}

// ---------------- K3: node finalize (mean + residual) + BN statistics ----------------
__global__ __launch_bounds__(256) void k_node(const float* __restrict__ node_attr,
                                              float* __restrict__ dout) {
  __shared__ float sP[106];
  int tid = threadIdx.x;
  if (tid < 106) sP[tid] = 0.f;
  __syncthreads();

  int n = blockIdx.x * blockDim.x + tid;
  bool valid = n < NNODE;
  float inv = 1.f;
  if (valid) inv = 1.f / fmaxf(g_cnt[n], 1.f);
  const float* srow  = g_sum + (valid ? (size_t)n * 78 : 0);
  const float* narow = node_attr + (valid ? (size_t)n * 78 : 0);

  for (int v = 0; v < 48; ++v) {
    float val = 0.f;
    if (valid) { val = srow[v] * inv + narow[v]; dout[(size_t)n * 78 + v] = val; }
    float s = val, qq = val * val;
#pragma unroll
    for (int o = 16; o; o >>= 1) {
      s += __shfl_xor_sync(0xffffffffu, s, o);
      qq += __shfl_xor_sync(0xffffffffu, qq, o);
    }
    if ((tid & 31) == 0) { atomicAdd(&sP[v], s); atomicAdd(&sP[48 + v], qq); }
  }
  for (int u = 0; u < 10; ++u) {
    float qq = 0.f;
    for (int i = 0; i < 3; ++i) {
      float val = 0.f;
      int c = 48 + u * 3 + i;
      if (valid) { val = srow[c] * inv + narow[c]; dout[(size_t)n * 78 + c] = val; }
      qq += val * val;
    }
#pragma unroll
    for (int o = 16; o; o >>= 1) qq += __shfl_xor_sync(0xffffffffu, qq, o);
    if ((tid & 31) == 0) atomicAdd(&sP[96 + u], qq);
  }
  __syncthreads();
  if (tid < 106) atomicAdd(&g_stats[tid], sP[tid]);
}

// ---------------- K4: apply batch norm in place ----------------
__global__ void k_bn(const float* __restrict__ bnw, const float* __restrict__ bnb,
                     float* __restrict__ dout) {
  int idx = blockIdx.x * blockDim.x + threadIdx.x;
  if (idx >= NNODE * 78) return;
  int c = idx % 78;
  float x = dout[idx];
  if (c < 48) {
    float mean = g_stats[c] * (1.f / NNODE);
    float var  = g_stats[48 + c] * (1.f / NNODE) - mean * mean;
    dout[idx] = (x - mean) * rsqrtf(var + EPS_BN) * bnw[c] + bnb[c];
  } else {
    int u = (c - 48) / 3;
    float vn = g_stats[96 + u] * (1.f / (3.f * NNODE));
    dout[idx] = x * rsqrtf(vn + EPS_BN) * bnw[48 + u];
  }
}

// ---------------- launch ----------------
extern "C" void kernel_launch(void* const* d_in, const int* in_sizes, int n_in,
                              void* d_out, int out_size) {
  const float* node_attr  = (const float*)d_in[0];
  const int*   edge_index = (const int*)d_in[1];
  const float* edge_attr  = (const float*)d_in[2];
  const float* edge_sh    = (const float*)d_in[3];
  const float* fc_w1      = (const float*)d_in[4];
  const float* fc_b1      = (const float*)d_in[5];
  const float* fc_w2      = (const float*)d_in[6];
  const float* fc_b2      = (const float*)d_in[7];
  const float* bn_w       = (const float*)d_in[8];
  const float* bn_b       = (const float*)d_in[9];
  float* out = (float*)d_out;

  cudaFuncSetAttribute(k_gemm1, cudaFuncAttributeMaxDynamicSharedMemorySize, K1_SMEM);
  cudaFuncSetAttribute(k_fused, cudaFuncAttributeMaxDynamicSharedMemorySize, K2_SMEM);

  k_zero<<<256, 256>>>();
  k_gemm1<<<NBLK, 512, K1_SMEM>>>(edge_attr, fc_w1, fc_b1);
  k_fused<<<NBLK, 512, K2_SMEM>>>(edge_index, node_attr, edge_sh, fc_w2, fc_b2);
  k_node<<<(NNODE + 255) / 256, 256>>>(node_attr, out);
  k_bn<<<(NNODE * 78 + 255) / 256, 256>>>(bn_w, bn_b, out);
}

// round 9
// speedup vs baseline: 2.2546x; 1.5788x over previous
#include <cuda_runtime.h>
#include <cuda_bf16.h>
#include <cstdint>

// ---------------- problem constants ----------------
static constexpr int NNODE = 10000;
static constexpr int NEDGE = 50000;
static constexpr int HID   = 128;
static constexpr int WTOT  = 3364;  // 2304 + 480 + 100 + 480
static constexpr int OFF2  = 2304;
static constexpr int OFF3  = 2784;
static constexpr int OFF4  = 2884;
static constexpr int TB    = 128;
static constexpr int NBLK  = (NEDGE + TB - 1) / TB;    // 391

#define EPS_BN     1e-5f
#define INV_SQRT3  0.57735026918962576f
#define NORM01     0.13130643285972254f   /* 1/sqrt(58) */

// ---------------- packed f32x2 helpers (k_gemm1 FFMA2 path) ----------------
__device__ __forceinline__ unsigned long long f2_fma(unsigned long long a,
                                                     unsigned long long b,
                                                     unsigned long long c) {
  unsigned long long d;
  asm("fma.rn.f32x2 %0, %1, %2, %3;" : "=l"(d) : "l"(a), "l"(b), "l"(c));
  return d;
}
__device__ __forceinline__ unsigned long long f2_dup(float x) {
  unsigned long long d;
  asm("mov.b64 %0, {%1, %1};" : "=l"(d) : "f"(x));
  return d;
}
__device__ __forceinline__ float2 f2_unpack(unsigned long long v) {
  float2 f;
  asm("mov.b64 {%0, %1}, %2;" : "=f"(f.x), "=f"(f.y) : "l"(v));
  return f;
}

// ---------------- mma.sync helper (Ampere-class HMMA, compiles for sm_103) ----------
__device__ __forceinline__ void mma16816(float* c, const uint32_t* a,
                                         uint32_t b0, uint32_t b1) {
  asm volatile(
      "mma.sync.aligned.m16n8k16.row.col.f32.bf16.bf16.f32 "
      "{%0,%1,%2,%3}, {%4,%5,%6,%7}, {%8,%9}, {%0,%1,%2,%3};"
      : "+f"(c[0]), "+f"(c[1]), "+f"(c[2]), "+f"(c[3])
      : "r"(a[0]), "r"(a[1]), "r"(a[2]), "r"(a[3]), "r"(b0), "r"(b1));
}

// bf16 tile layout: row-major, 64 k-words (bf16x2) per row, pitch 68 words (272 B),
// with per-octet XOR swizzle on the k-word index -> conflict-free fragment loads
// AND conflict-free strided tile builds.
__device__ __forceinline__ uint32_t toff(int row, int kp) {
  return (uint32_t)(row * 68 + (kp ^ ((row >> 3) & 3))) * 4u;
}

// bf16 hi/lo split
__device__ __forceinline__ void bsplit(float x, __nv_bfloat16& hi, __nv_bfloat16& lo) {
  hi = __float2bfloat16(x);
  lo = __float2bfloat16(x - __bfloat162float(hi));
}

// ---------------- scratch ----------------
__device__ float g_hT[(size_t)HID * NEDGE];   // h transposed [k][e]
__device__ float g_sum[(size_t)NNODE * 78];
__device__ float g_cnt[NNODE];
__device__ float g_stats[106];

// ---------------- K0: zero scratch ----------------
__global__ void k_zero() {
  int idx = blockIdx.x * blockDim.x + threadIdx.x;
  int stride = gridDim.x * blockDim.x;
  for (int i = idx; i < NNODE * 78; i += stride) g_sum[i] = 0.f;
  for (int i = idx; i < NNODE; i += stride) g_cnt[i] = 0.f;
  if (idx < 106) g_stats[idx] = 0.f;
}

// ---------------- K1: h = relu(edge_attr @ W1 + b1), stored transposed ----------------
static constexpr int K1_SMEM = (128 * 132 + 128 * 128) * 4;

__global__ __launch_bounds__(512) void k_gemm1(const float* __restrict__ A,
                                               const float* __restrict__ W1,
                                               const float* __restrict__ b1) {
  extern __shared__ float sm[];
  float* sAT = sm;              // [128 k][132 e]; reused as [e][132 c]
  float* sB  = sm + 128 * 132;  // [128 k][128 c]
  int tid = threadIdx.x;
  int e0 = blockIdx.x * TB;

  for (int idx = tid; idx < 128 * 128; idx += 512) {
    int e = idx >> 7, k = idx & 127;
    sAT[k * 132 + e] = (e0 + e < NEDGE) ? A[(size_t)(e0 + e) * 128 + k] : 0.f;
    sB[idx] = W1[idx];
  }
  __syncthreads();

  int w = tid >> 5, lane = tid & 31;
  int ea = w * 4, ca = lane * 4;

  unsigned long long C2[4][4];
#pragma unroll
  for (int i = 0; i < 4; ++i)
#pragma unroll
    for (int j = 0; j < 4; ++j) C2[i][j] = 0ull;

#pragma unroll 3
  for (int k = 0; k < 128; ++k) {
    ulonglong2 a0 = *(const ulonglong2*)&sAT[k * 132 + ea];
    ulonglong2 a1 = *(const ulonglong2*)&sAT[k * 132 + 64 + ea];
    float4 B = *(const float4*)&sB[k * 128 + ca];
    unsigned long long bd0 = f2_dup(B.x), bd1 = f2_dup(B.y),
                       bd2 = f2_dup(B.z), bd3 = f2_dup(B.w);
    C2[0][0] = f2_fma(a0.x, bd0, C2[0][0]); C2[0][1] = f2_fma(a0.x, bd1, C2[0][1]);
    C2[0][2] = f2_fma(a0.x, bd2, C2[0][2]); C2[0][3] = f2_fma(a0.x, bd3, C2[0][3]);
    C2[1][0] = f2_fma(a0.y, bd0, C2[1][0]); C2[1][1] = f2_fma(a0.y, bd1, C2[1][1]);
    C2[1][2] = f2_fma(a0.y, bd2, C2[1][2]); C2[1][3] = f2_fma(a0.y, bd3, C2[1][3]);
    C2[2][0] = f2_fma(a1.x, bd0, C2[2][0]); C2[2][1] = f2_fma(a1.x, bd1, C2[2][1]);
    C2[2][2] = f2_fma(a1.x, bd2, C2[2][2]); C2[2][3] = f2_fma(a1.x, bd3, C2[2][3]);
    C2[3][0] = f2_fma(a1.y, bd0, C2[3][0]); C2[3][1] = f2_fma(a1.y, bd1, C2[3][1]);
    C2[3][2] = f2_fma(a1.y, bd2, C2[3][2]); C2[3][3] = f2_fma(a1.y, bd3, C2[3][3]);
  }
  __syncthreads();

  float b0 = b1[ca], bb1 = b1[ca + 1], bb2 = b1[ca + 2], bb3 = b1[ca + 3];
#pragma unroll
  for (int i = 0; i < 4; ++i) {
    int er = (i < 2) ? (ea + 2 * i) : (64 + ea + 2 * (i - 2));
    float2 f0 = f2_unpack(C2[i][0]);
    float2 f1 = f2_unpack(C2[i][1]);
    float2 f2v = f2_unpack(C2[i][2]);
    float2 f3 = f2_unpack(C2[i][3]);
    *(float4*)&sAT[er * 132 + ca] =
        make_float4(fmaxf(f0.x + b0, 0.f), fmaxf(f1.x + bb1, 0.f),
                    fmaxf(f2v.x + bb2, 0.f), fmaxf(f3.x + bb3, 0.f));
    *(float4*)&sAT[(er + 1) * 132 + ca] =
        make_float4(fmaxf(f0.y + b0, 0.f), fmaxf(f1.y + bb1, 0.f),
                    fmaxf(f2v.y + bb2, 0.f), fmaxf(f3.y + bb3, 0.f));
  }
  __syncthreads();
  for (int idx = tid; idx < 128 * 128; idx += 512) {
    int c = idx >> 7, e = idx & 127;
    if (e0 + e < NEDGE) g_hT[(size_t)c * NEDGE + e0 + e] = sAT[e * 132 + c];
  }
}

// ---------------- K2: fused HMMA GEMM2 (bf16x3) + tensor product + scatter --------
// smem byte layout
static constexpr int TILE_B  = 128 * 68 * 4;            // 34816 per bf16 tile
static constexpr int SM_AHI  = 0;
static constexpr int SM_ALO  = TILE_B;                  // 34816
static constexpr int SM_BHI  = 2 * TILE_B;              // 69632  (also sC staging)
static constexpr int SM_BLO  = 3 * TILE_B;              // 104448
static constexpr int SM_TPF  = 4 * TILE_B;              // 139264
static constexpr int FS_S    = SM_TPF / 4;              // 128*48
static constexpr int FS_DOT  = FS_S + 128 * 48;
static constexpr int FS_VIN  = FS_DOT + 128 * 10;
static constexpr int FS_SH   = FS_VIN + 128 * 30;
static constexpr int FS_AC0  = FS_SH + 128 * 4;
static constexpr int FS_YA   = FS_AC0 + 128 * 48;
static constexpr int FS_YB   = FS_YA + 128 * 10;
static constexpr int SM_BIAS = (FS_YB + 128 * 30) * 4;  // 231424
static constexpr int K2_SMEM = SM_BIAS + 512;           // 231936

__global__ __launch_bounds__(512) void k_fused(const int* __restrict__ eidx,
                                               const float* __restrict__ node_attr,
                                               const float* __restrict__ edge_sh,
                                               const float* __restrict__ W2,
                                               const float* __restrict__ b2) {
  extern __shared__ char smem[];
  float* smf   = (float*)smem;
  float* sC    = (float*)(smem + SM_BHI);   // C staging, pitch 132 (overlays B)
  float* sS    = smf + FS_S;
  float* sDot  = smf + FS_DOT;
  float* sVin  = smf + FS_VIN;
  float* sSh   = smf + FS_SH;
  float* sAc0  = smf + FS_AC0;
  float* sYa   = smf + FS_YA;
  float* sYb   = smf + FS_YB;
  float* sBias = (float*)(smem + SM_BIAS);

  int tid = threadIdx.x;
  int wid = tid >> 5, lane = tid & 31;
  int e0 = blockIdx.x * TB;

  // ---- build A_hi / A_lo tiles from g_hT (once per block) ----
  for (int idx = tid; idx < 64 * 128; idx += 512) {
    int kp = idx >> 7, e = idx & 127;
    int eg = e0 + e;
    float x0 = 0.f, x1 = 0.f;
    if (eg < NEDGE) {
      x0 = g_hT[(size_t)(2 * kp) * NEDGE + eg];
      x1 = g_hT[(size_t)(2 * kp + 1) * NEDGE + eg];
    }
    __nv_bfloat16 h0, l0, h1, l1;
    bsplit(x0, h0, l0);
    bsplit(x1, h1, l1);
    __nv_bfloat162 h2; h2.x = h0; h2.y = h1;
    __nv_bfloat162 l2; l2.x = l0; l2.y = l1;
    uint32_t off = toff(e, kp);
    *(__nv_bfloat162*)(smem + SM_AHI + off) = h2;
    *(__nv_bfloat162*)(smem + SM_ALO + off) = l2;
  }

  // zero accumulators (contiguous sAc0, sYa, sYb)
  for (int idx = tid; idx < 128 * (48 + 10 + 30); idx += 512) sAc0[idx] = 0.f;

  int e_ = tid >> 2, q = tid & 3;   // 4 owner threads per edge

  // left vectors
  {
    int eg = e0 + e_;
    if (eg < NEDGE) {
      int dst = eidx[NEDGE + eg];
      const float* x = node_attr + (size_t)dst * 78;
      for (int u = q * 12; u < q * 12 + 12; ++u) sS[e_ * 48 + u] = x[u];
      for (int m = q; m < 30; m += 4) sVin[e_ * 30 + m] = x[48 + m];
      if (q == 0)
        for (int i = 0; i < 4; ++i) sSh[e_ * 4 + i] = edge_sh[(size_t)eg * 4 + i];
    }
  }
  __syncthreads();
  {
    float s1 = sSh[e_ * 4 + 1], s2 = sSh[e_ * 4 + 2], s3 = sSh[e_ * 4 + 3];
    for (int u = q; u < 10; u += 4)
      sDot[e_ * 10 + u] = (sVin[e_ * 30 + u * 3] * s1 + sVin[e_ * 30 + u * 3 + 1] * s2 +
                           sVin[e_ * 30 + u * 3 + 2] * s3) * INV_SQRT3;
  }

  // warp tiling: 4x4 warp grid, each warp owns a 32(m) x 32(n) C tile
  int m0 = (wid >> 2) * 32;
  int n0 = (wid & 3) * 32;
  int g = lane >> 2, t = lane & 3;

  // chunk schedule: 4x w2(120) -> [scale sS by sh0] -> 18x w1(128) -> 4x w4(120) -> 1x w3(100)
  for (int ci = 0; ci < 27; ++ci) {
    int type, jstart, cnt, rel;
    if (ci < 4)       { type = 2; rel = ci * 120;        jstart = OFF2 + rel; cnt = 120; }
    else if (ci < 22) { type = 1; rel = (ci - 4) * 128;  jstart = rel;        cnt = 128; }
    else if (ci < 26) { type = 4; rel = (ci - 22) * 120; jstart = OFF4 + rel; cnt = 120; }
    else              { type = 3; rel = 0;               jstart = OFF3;       cnt = 100; }

    __syncthreads();   // prior epilogue done with sC before overwriting B region

    // ---- build B^T tiles: sB[j][k] = W2[k][jstart+j], hi/lo split ----
    for (int idx = tid; idx < 64 * 128; idx += 512) {
      int kp = idx >> 7, j = idx & 127;
      float x0 = 0.f, x1 = 0.f;
      if (j < cnt) {
        x0 = W2[(size_t)(2 * kp) * WTOT + jstart + j];
        x1 = W2[(size_t)(2 * kp + 1) * WTOT + jstart + j];
      }
      __nv_bfloat16 h0, l0, h1, l1;
      bsplit(x0, h0, l0);
      bsplit(x1, h1, l1);
      __nv_bfloat162 h2; h2.x = h0; h2.y = h1;
      __nv_bfloat162 l2; l2.x = l0; l2.y = l1;
      uint32_t off = toff(j, kp);
      *(__nv_bfloat162*)(smem + SM_BHI + off) = h2;
      *(__nv_bfloat162*)(smem + SM_BLO + off) = l2;
    }
    if (tid < 128) sBias[tid] = (tid < cnt) ? b2[jstart + tid] : 0.f;
    __syncthreads();   // B tiles + bias ready

    // ---- 3-pass HMMA: acc = Ah*Bh + Ah*Bl + Al*Bh (fp32 accum in regs) ----
    float acc[2][4][4];
#pragma unroll
    for (int mi = 0; mi < 2; ++mi)
#pragma unroll
      for (int ni = 0; ni < 4; ++ni)
#pragma unroll
        for (int r = 0; r < 4; ++r) acc[mi][ni][r] = 0.f;

#pragma unroll
    for (int pass = 0; pass < 3; ++pass) {
      const char* pA = smem + ((pass == 2) ? SM_ALO : SM_AHI);
      const char* pB = smem + ((pass == 1) ? SM_BLO : SM_BHI);
#pragma unroll
      for (int ks = 0; ks < 8; ++ks) {
        int kp0 = ks * 8 + t;
        uint32_t a[2][4];
#pragma unroll
        for (int mi = 0; mi < 2; ++mi) {
          int row = m0 + mi * 16 + g;
          a[mi][0] = *(const uint32_t*)(pA + toff(row,     kp0));
          a[mi][1] = *(const uint32_t*)(pA + toff(row + 8, kp0));
          a[mi][2] = *(const uint32_t*)(pA + toff(row,     kp0 + 4));
          a[mi][3] = *(const uint32_t*)(pA + toff(row + 8, kp0 + 4));
        }
#pragma unroll
        for (int ni = 0; ni < 4; ++ni) {
          int n = n0 + ni * 8 + g;
          uint32_t b0 = *(const uint32_t*)(pB + toff(n, kp0));
          uint32_t b1 = *(const uint32_t*)(pB + toff(n, kp0 + 4));
          mma16816(acc[0][ni], a[0], b0, b1);
          mma16816(acc[1][ni], a[1], b0, b1);
        }
      }
    }
    __syncthreads();   // all MMA reads of sB done before sC overwrite

    // ---- C fragments + bias -> sC staging (pitch 132) ----
#pragma unroll
    for (int mi = 0; mi < 2; ++mi) {
      int row = m0 + mi * 16 + g;
#pragma unroll
      for (int ni = 0; ni < 4; ++ni) {
        int col = n0 + ni * 8 + 2 * t;
        float bx = sBias[col], by = sBias[col + 1];
        *(float2*)&sC[row * 132 + col] =
            make_float2(acc[mi][ni][0] + bx, acc[mi][ni][1] + by);
        *(float2*)&sC[(row + 8) * 132 + col] =
            make_float2(acc[mi][ni][2] + bx, acc[mi][ni][3] + by);
      }
    }
    __syncthreads();   // sC complete

    // ---- ownership-partitioned TP epilogue (4 threads per edge) ----
    if (type == 1 || type == 4) {
      const float* mult = (type == 1) ? (sS + e_ * 48) : (sDot + e_ * 10);
      int umax = (type == 1) ? 47 : 9;
      const float* Cs = sC + e_ * 132 - rel;
#pragma unroll 4
      for (int vv = 0; vv < 12; ++vv) {
        int v = q * 12 + vv;
        int d = rel - v;
        int u0 = d > 0 ? (d + 47) / 48 : 0;
        int u1 = (rel + cnt - 1 - v) / 48; if (u1 > umax) u1 = umax;
        float p = 0.f;
        for (int u = u0; u <= u1; ++u) p = fmaf(Cs[u * 48 + v], mult[u], p);
        sAc0[e_ * 48 + v] += p;
      }
    } else if (type == 2) {
      const float* Cs = sC + e_ * 132 - rel;
      for (int v = q; v < 10; v += 4) {
        int d = rel - v;
        int u0 = d > 0 ? (d + 9) / 10 : 0;
        int u1 = (rel + cnt - 1 - v) / 10; if (u1 > 47) u1 = 47;
        float p = 0.f;
        for (int u = u0; u <= u1; ++u) p = fmaf(Cs[u * 10 + v], sS[e_ * 48 + u], p);
        sYa[e_ * 10 + v] += p;
      }
    } else {  // w3
      const float* Cs = sC + e_ * 132;
      for (int v = q; v < 10; v += 4) {
        float y0 = 0.f, y1 = 0.f, y2 = 0.f;
#pragma unroll
        for (int u = 0; u < 10; ++u) {
          float wv = Cs[u * 10 + v];
          y0 = fmaf(wv, sVin[e_ * 30 + u * 3 + 0], y0);
          y1 = fmaf(wv, sVin[e_ * 30 + u * 3 + 1], y1);
          y2 = fmaf(wv, sVin[e_ * 30 + u * 3 + 2], y2);
        }
        sYb[e_ * 30 + v * 3 + 0] += y0;
        sYb[e_ * 30 + v * 3 + 1] += y1;
        sYb[e_ * 30 + v * 3 + 2] += y2;
      }
    }

    if (ci == 3) {  // w2 phase done -> scale s by sh0 for the w1 phase
      __syncthreads();
      float s0 = sSh[e_ * 4 + 0];
      for (int vv = 0; vv < 12; ++vv) sS[e_ * 48 + q * 12 + vv] *= s0;
    }
  }
  __syncthreads();

  // ---- final per-edge output + scatter to node sums ----
  {
    int eg = e0 + e_;
    if (eg < NEDGE) {
      int src = eidx[eg];
      float s0 = sSh[e_ * 4], s1 = sSh[e_ * 4 + 1], s2 = sSh[e_ * 4 + 2], s3 = sSh[e_ * 4 + 3];
      float* dp = g_sum + (size_t)src * 78;
      for (int vv = 0; vv < 12; ++vv) {
        int v = q * 12 + vv;
        atomicAdd(&dp[v], sAc0[e_ * 48 + v] * NORM01);
      }
      for (int v = q; v < 10; v += 4) {
        float ya = sYa[e_ * 10 + v];
        atomicAdd(&dp[48 + v * 3 + 0], (ya * s1 + sYb[e_ * 30 + v * 3 + 0] * s0) * NORM01);
        atomicAdd(&dp[48 + v * 3 + 1], (ya * s2 + sYb[e_ * 30 + v * 3 + 1] * s0) * NORM01);
        atomicAdd(&dp[48 + v * 3 + 2], (ya * s3 + sYb[e_ * 30 + v * 3 + 2] * s0) * NORM01);
      }
      if (q == 0) atomicAdd(&g_cnt[src], 1.f);
    }
  }
}

// ---------------- K3: node finalize (mean + residual) + BN statistics ----------------
__global__ __launch_bounds__(256) void k_node(const float* __restrict__ node_attr,
                                              float* __restrict__ dout) {
  __shared__ float sP[106];
  int tid = threadIdx.x;
  if (tid < 106) sP[tid] = 0.f;
  __syncthreads();

  int n = blockIdx.x * blockDim.x + tid;
  bool valid = n < NNODE;
  float inv = 1.f;
  if (valid) inv = 1.f / fmaxf(g_cnt[n], 1.f);
  const float* srow  = g_sum + (valid ? (size_t)n * 78 : 0);
  const float* narow = node_attr + (valid ? (size_t)n * 78 : 0);

  for (int v = 0; v < 48; ++v) {
    float val = 0.f;
    if (valid) { val = srow[v] * inv + narow[v]; dout[(size_t)n * 78 + v] = val; }
    float s = val, qq = val * val;
#pragma unroll
    for (int o = 16; o; o >>= 1) {
      s += __shfl_xor_sync(0xffffffffu, s, o);
      qq += __shfl_xor_sync(0xffffffffu, qq, o);
    }
    if ((tid & 31) == 0) { atomicAdd(&sP[v], s); atomicAdd(&sP[48 + v], qq); }
  }
  for (int u = 0; u < 10; ++u) {
    float qq = 0.f;
    for (int i = 0; i < 3; ++i) {
      float val = 0.f;
      int c = 48 + u * 3 + i;
      if (valid) { val = srow[c] * inv + narow[c]; dout[(size_t)n * 78 + c] = val; }
      qq += val * val;
    }
#pragma unroll
    for (int o = 16; o; o >>= 1) qq += __shfl_xor_sync(0xffffffffu, qq, o);
    if ((tid & 31) == 0) atomicAdd(&sP[96 + u], qq);
  }
  __syncthreads();
  if (tid < 106) atomicAdd(&g_stats[tid], sP[tid]);
}

// ---------------- K4: apply batch norm in place ----------------
__global__ void k_bn(const float* __restrict__ bnw, const float* __restrict__ bnb,
                     float* __restrict__ dout) {
  int idx = blockIdx.x * blockDim.x + threadIdx.x;
  if (idx >= NNODE * 78) return;
  int c = idx % 78;
  float x = dout[idx];
  if (c < 48) {
    float mean = g_stats[c] * (1.f / NNODE);
    float var  = g_stats[48 + c] * (1.f / NNODE) - mean * mean;
    dout[idx] = (x - mean) * rsqrtf(var + EPS_BN) * bnw[c] + bnb[c];
  } else {
    int u = (c - 48) / 3;
    float vn = g_stats[96 + u] * (1.f / (3.f * NNODE));
    dout[idx] = x * rsqrtf(vn + EPS_BN) * bnw[48 + u];
  }
}

// ---------------- launch ----------------
extern "C" void kernel_launch(void* const* d_in, const int* in_sizes, int n_in,
                              void* d_out, int out_size) {
  const float* node_attr  = (const float*)d_in[0];
  const int*   edge_index = (const int*)d_in[1];
  const float* edge_attr  = (const float*)d_in[2];
  const float* edge_sh    = (const float*)d_in[3];
  const float* fc_w1      = (const float*)d_in[4];
  const float* fc_b1      = (const float*)d_in[5];
  const float* fc_w2      = (const float*)d_in[6];
  const float* fc_b2      = (const float*)d_in[7];
  const float* bn_w       = (const float*)d_in[8];
  const float* bn_b       = (const float*)d_in[9];
  float* out = (float*)d_out;

  cudaFuncSetAttribute(k_gemm1, cudaFuncAttributeMaxDynamicSharedMemorySize, K1_SMEM);
  cudaFuncSetAttribute(k_fused, cudaFuncAttributeMaxDynamicSharedMemorySize, K2_SMEM);

  k_zero<<<256, 256>>>();
  k_gemm1<<<NBLK, 512, K1_SMEM>>>(edge_attr, fc_w1, fc_b1);
  k_fused<<<NBLK, 512, K2_SMEM>>>(edge_index, node_attr, edge_sh, fc_w2, fc_b2);
  k_node<<<(NNODE + 255) / 256, 256>>>(node_attr, out);
  k_bn<<<(NNODE * 78 + 255) / 256, 256>>>(bn_w, bn_b, out);
}